// round 2
// baseline (speedup 1.0000x reference)
#include <cuda_runtime.h>
#include <math.h>

#define B 8192
#define NTHREADS 512
#define PER_THREAD (B / NTHREADS)   // 16

#define MARGIN 0.1f
#define THRESH 0.5f
#define SCALE_POS 2.0f
#define SCALE_NEG 40.0f
#define POS_THR (1.0f - 1e-5f)

// Scratch (no allocations allowed in kernel_launch)
__device__ float g_row_loss[B];

// ---------------------------------------------------------------------------
// Kernel 1: one CTA per row. Row elements live in registers; two logical
// passes but a single HBM read of sim_mat. Labels (32 KB, int32) are
// L2-resident and read directly.
// ---------------------------------------------------------------------------
__global__ __launch_bounds__(NTHREADS) void ms_loss_rows_kernel(
    const float* __restrict__ sim,
    const int*   __restrict__ lab
) {
    const int row = blockIdx.x;
    const int tid = threadIdx.x;
    const int lane = tid & 31;
    const int warp = tid >> 5;                 // 16 warps

    const float* __restrict__ srow = sim + (size_t)row * B;
    const int lab_i = __ldg(&lab[row]);

    // ---- load row slice into registers + label-eq bitmask ----
    float    s[PER_THREAD];
    unsigned eqm = 0u;
    #pragma unroll
    for (int k = 0; k < PER_THREAD; k++) {
        const int j = tid + k * NTHREADS;      // coalesced 128B/warp
        s[k] = srow[j];
        eqm |= (unsigned)(__ldg(&lab[j]) == lab_i) << k;
    }

    // ---- pass 1: hardest positive (min) / hardest negative (max) ----
    float mn =  INFINITY;
    float mx = -INFINITY;
    #pragma unroll
    for (int k = 0; k < PER_THREAD; k++) {
        const bool eq = (eqm >> k) & 1u;
        const float v = s[k];
        if (eq) {
            if (v < POS_THR) mn = fminf(mn, v);
        } else {
            mx = fmaxf(mx, v);
        }
    }

    // warp reduce
    #pragma unroll
    for (int o = 16; o > 0; o >>= 1) {
        mn = fminf(mn, __shfl_xor_sync(0xffffffffu, mn, o));
        mx = fmaxf(mx, __shfl_xor_sync(0xffffffffu, mx, o));
    }

    __shared__ float sm_a[16];
    __shared__ float sm_b[16];
    if (lane == 0) { sm_a[warp] = mn; sm_b[warp] = mx; }
    __syncthreads();

    float min_pos =  INFINITY;
    float max_neg = -INFINITY;
    #pragma unroll
    for (int w = 0; w < 16; w++) {
        min_pos = fminf(min_pos, sm_a[w]);
        max_neg = fmaxf(max_neg, sm_b[w]);
    }

    // ---- pass 2 (registers only): mined exponential sums ----
    float ps = 0.0f, ns = 0.0f;
    #pragma unroll
    for (int k = 0; k < PER_THREAD; k++) {
        const bool eq = (eqm >> k) & 1u;
        const float v = s[k];
        if (eq) {
            // sel_pos = pos_mask & (sim - MARGIN < max_neg)
            if (v < POS_THR && (v - MARGIN) < max_neg)
                ps += __expf(-SCALE_POS * (v - THRESH));
        } else {
            // sel_neg = neg_mask & (sim + MARGIN > min_pos)
            if ((v + MARGIN) > min_pos)
                ns += __expf(SCALE_NEG * (v - THRESH));
        }
    }

    #pragma unroll
    for (int o = 16; o > 0; o >>= 1) {
        ps += __shfl_xor_sync(0xffffffffu, ps, o);
        ns += __shfl_xor_sync(0xffffffffu, ns, o);
    }

    __syncthreads();   // protect sm_a/sm_b reuse
    if (lane == 0) { sm_a[warp] = ps; sm_b[warp] = ns; }
    __syncthreads();

    if (tid == 0) {
        float P = 0.0f, N = 0.0f;
        #pragma unroll
        for (int w = 0; w < 16; w++) { P += sm_a[w]; N += sm_b[w]; }
        // exp terms are strictly positive and never underflow in fp32,
        // so valid <=> (P > 0 && N > 0)
        float loss = 0.0f;
        if (P > 0.0f && N > 0.0f)
            loss = log1pf(P) * (1.0f / SCALE_POS) + log1pf(N) * (1.0f / SCALE_NEG);
        g_row_loss[row] = loss;
    }
}

// ---------------------------------------------------------------------------
// Kernel 2: deterministic final reduction of 8192 per-row losses
// ---------------------------------------------------------------------------
__global__ void reduce_loss_kernel(float* __restrict__ out) {
    __shared__ float sm[1024];
    const int tid = threadIdx.x;
    float a = 0.0f;
    #pragma unroll
    for (int i = tid; i < B; i += 1024) a += g_row_loss[i];
    sm[tid] = a;
    __syncthreads();
    #pragma unroll
    for (int stride = 512; stride > 0; stride >>= 1) {
        if (tid < stride) sm[tid] += sm[tid + stride];
        __syncthreads();
    }
    if (tid == 0) out[0] = sm[0] / (float)B;
}

// ---------------------------------------------------------------------------
extern "C" void kernel_launch(void* const* d_in, const int* in_sizes, int n_in,
                              void* d_out, int out_size) {
    const float* sim = (const float*)d_in[0];
    const int*   lab = (const int*)d_in[1];    // JAX x64 disabled -> int32
    float*       out = (float*)d_out;

    ms_loss_rows_kernel<<<B, NTHREADS>>>(sim, lab);
    reduce_loss_kernel<<<1, 1024>>>(out);
}